// round 5
// baseline (speedup 1.0000x reference)
#include <cuda_runtime.h>

// YOLO loss, flat one-wave: grid (4,3,32) = 384 blocks x 256 threads.
// blockIdx.z = batch b, blockIdx.y = level, blockIdx.x = quarter of the
// 1000 float4-chunk items for that (b,lvl). Thread q = quarter*256+tid < 1000:
// m = q/20, chunk = q%20. chunk==0 thread also does GIoU.
// Deterministic partials + last-block-done reduction.

#define NPART 384
#define NTHREADS 256

__device__ float g_box_part[NPART];
__device__ float g_cls_part[NPART];
__device__ int   g_np_part[NPART];
__device__ unsigned int g_done = 0;

__device__ __forceinline__ float warp_sum(float v) {
    #pragma unroll
    for (int o = 16; o > 0; o >>= 1) v += __shfl_down_sync(0xffffffffu, v, o);
    return v;
}

__global__ void __launch_bounds__(NTHREADS) yolo_flat(
    const float* __restrict__ box_preds,   // [32, 8400, 4]
    const float* __restrict__ cls_preds,   // [32, 8400, 80]
    const float* __restrict__ gt_boxes,    // [32, 50, 4]
    const int*   __restrict__ gt_labels,   // [32, 50]
    const void*  __restrict__ gt_mask,     // [32, 50] bool (byte or int32 layout)
    float*       __restrict__ out)
{
    const int tid  = threadIdx.x;
    const int lane = tid & 31;
    const int wrp  = tid >> 5;
    const int lvl  = blockIdx.y;
    const int b    = blockIdx.z;
    const int q    = blockIdx.x * NTHREADS + tid;   // 0..1023, guard < 1000

    // level constants (branchless selects)
    const int  W      = (lvl == 0) ? 80 : (lvl == 1) ? 40 : 20;
    const int  offset = (lvl == 0) ? 0  : (lvl == 1) ? 6400 : 8000;
    const float inv_s = (lvl == 0) ? 0.125f : (lvl == 1) ? 0.0625f : 0.03125f;

    const int m     = q / 20;          // 0..49
    const int chunk = q - m * 20;      // 0..19

    float cls_acc = 0.0f;
    float box_acc = 0.0f;
    bool  pos     = false;

    if (q < 1000) {
        const int gtoff = b * 50 + m;
        const float4 gb = __ldg((const float4*)(gt_boxes + (size_t)gtoff * 4));
        const int lab = __ldg(gt_labels + gtoff);

        bool mk;
        {
            const int first = *(const int*)gt_mask;   // broadcast dtype probe
            if ((unsigned)first <= 1u)
                mk = ((const int*)gt_mask)[gtoff] != 0;
            else
                mk = ((const unsigned char*)gt_mask)[gtoff] != 0;
        }

        const float x1 = gb.x, y1 = gb.y, x2 = gb.z, y2 = gb.w;
        const int gi = (int)floorf((x1 + x2) * 0.5f * inv_s);
        const int gj = (int)floorf((y1 + y2) * 0.5f * inv_s);
        const bool valid = mk && (gi >= 0) && (gj >= 0) && (gi < W) && (gj < W);
        const int idx = valid ? (offset + gj * W + gi) : 0;

        if (valid) {
            const size_t row = (size_t)b * 8400 + idx;
            const float4 xv = __ldg((const float4*)(cls_preds + row * 80 + chunk * 4));
            const int c4 = chunk * 4;
            const float xs[4] = {xv.x, xv.y, xv.z, xv.w};
            #pragma unroll
            for (int k = 0; k < 4; k++) {
                const float x = xs[k];
                const float e = __expf(-x);
                const float inv = 1.0f / (1.0f + e);
                const float L = __logf(1.0f + e);        // softplus(-x)
                if (c4 + k == lab) {
                    const float qq = e * inv;            // 1 - sigmoid(x)
                    cls_acc += 0.25f * qq * qq * L;
                } else {
                    const float p = inv;                 // sigmoid(x)
                    cls_acc += 0.75f * p * p * (x + L);  // softplus(x)
                }
            }

            if (chunk == 0) {
                pos = true;
                const float4 pbv = __ldg((const float4*)(box_preds + row * 4));
                const float px1 = pbv.x, py1 = pbv.y, px2 = pbv.z, py2 = pbv.w;
                const float ix1 = fmaxf(px1, x1), iy1 = fmaxf(py1, y1);
                const float ix2 = fminf(px2, x2), iy2 = fminf(py2, y2);
                const float inter = fmaxf(ix2 - ix1, 0.0f) * fmaxf(iy2 - iy1, 0.0f);
                const float a1 = (px2 - px1) * (py2 - py1);
                const float a2 = (x2 - x1) * (y2 - y1);
                const float uni = a1 + a2 - inter;
                const float iou = inter / uni;
                const float ex1 = fminf(px1, x1), ey1 = fminf(py1, y1);
                const float ex2 = fmaxf(px2, x2), ey2 = fmaxf(py2, y2);
                const float encl = (ex2 - ex1) * (ey2 - ey1);
                box_acc = 1.0f - (iou - (encl - uni) / encl);
            }
        }
    }

    // Block reduction: 2 float warp sums + popc(ballot) for np
    __shared__ float w0[8], w1[8];
    __shared__ int   w2[8];
    const float rb = warp_sum(box_acc);
    const float rc = warp_sum(cls_acc);
    const int   rn = __popc(__ballot_sync(0xffffffffu, pos));
    if (lane == 0) { w0[wrp] = rb; w1[wrp] = rc; w2[wrp] = rn; }
    __syncthreads();

    const int blk = (b * 3 + lvl) * 4 + blockIdx.x;   // 0..383
    if (wrp == 0) {
        float vb = (lane < 8) ? w0[lane] : 0.0f;
        float vc = (lane < 8) ? w1[lane] : 0.0f;
        int   vn = (lane < 8) ? w2[lane] : 0;
        vb = warp_sum(vb); vc = warp_sum(vc);
        #pragma unroll
        for (int o = 4; o > 0; o >>= 1) vn += __shfl_down_sync(0xffffffffu, vn, o);
        if (lane == 0) {
            g_box_part[blk] = vb;
            g_cls_part[blk] = vc;
            g_np_part[blk]  = vn;
        }
    }

    // Last-block-done final reduction over 384 partials
    __shared__ bool s_last;
    __threadfence();
    if (tid == 0) {
        unsigned old = atomicAdd(&g_done, 1u);
        s_last = (old == NPART - 1);
    }
    __syncthreads();
    if (s_last) {
        float vb = *((volatile float*)&g_box_part[tid]);
        float vc = *((volatile float*)&g_cls_part[tid]);
        int   vn = *((volatile int*)&g_np_part[tid]);
        if (tid < NPART - NTHREADS) {
            vb += *((volatile float*)&g_box_part[tid + NTHREADS]);
            vc += *((volatile float*)&g_cls_part[tid + NTHREADS]);
            vn += *((volatile int*)&g_np_part[tid + NTHREADS]);
        }
        vb = warp_sum(vb); vc = warp_sum(vc);
        #pragma unroll
        for (int o = 16; o > 0; o >>= 1) vn += __shfl_down_sync(0xffffffffu, vn, o);
        if (lane == 0) { w0[wrp] = vb; w1[wrp] = vc; w2[wrp] = vn; }
        __syncthreads();
        if (tid == 0) {
            float sb = 0.0f, sc = 0.0f; int sn = 0;
            #pragma unroll
            for (int i = 0; i < 8; i++) { sb += w0[i]; sc += w1[i]; sn += w2[i]; }
            const float denom = (float)(sn > 1 ? sn : 1);
            out[0] = (5.0f * sb + sc) / denom;
            g_done = 0;   // reset for next graph replay
        }
    }
}

extern "C" void kernel_launch(void* const* d_in, const int* in_sizes, int n_in,
                              void* d_out, int out_size)
{
    const float* box_preds = (const float*)d_in[0];
    const float* cls_preds = (const float*)d_in[1];
    const float* gt_boxes  = (const float*)d_in[2];
    const int*   gt_labels = (const int*)d_in[3];
    const void*  gt_mask   = d_in[4];
    float* out = (float*)d_out;

    dim3 grid(4, 3, 32);
    yolo_flat<<<grid, NTHREADS>>>(box_preds, cls_preds, gt_boxes, gt_labels, gt_mask, out);
}